// round 11
// baseline (speedup 1.0000x reference)
#include <cuda_runtime.h>
#include <cuda_bf16.h>

#define BATCH 2
#define NSEQ 1024
#define DIM 256
#define PDIM 64
#define MAXREL 32
#define NEMBED (2 * MAXREL + 1)
#define NROWS (BATCH * NSEQ)
#define IT 4      // i-rows per block in pair_kernel
#define PROWS 2   // rows per block in proj_kernel

// Scratch
__device__ float g_proj_i[NROWS * PDIM];
__device__ float g_proj_j[NROWS * PDIM];
__device__ float g_proj_jT[BATCH * PDIM * NSEQ];   // [b][p][j] transposed copy
__device__ __align__(16) float2 g_mt_i[NROWS];     // {mean, mean-of-squares}
__device__ __align__(16) float2 g_mt_j[NROWS];

// ---------------------------------------------------------------------------
// Kernel 1: projections. Thread = (row, 2 adjacent cols) -> W reads via
// LDG.64 (halves LDG instruction count vs scalar; binding resource is the
// 1.82 cyc/LDG SM issue floor). grid=1024, 4096 warps -> occ ~43%.
// ---------------------------------------------------------------------------
__global__ __launch_bounds__(128) void proj_kernel(
    const float* __restrict__ single, const float* __restrict__ W,
    const float* __restrict__ bias)
{
    __shared__ __align__(16) float s[PROWS][DIM];   // 2 KB
    const int rb = blockIdx.x * PROWS;
    const int t = threadIdx.x;

    // stage 2 rows of single: 128 float4, one per thread, coalesced
    ((float4*)s)[t] = ((const float4*)(single + (size_t)rb * DIM))[t];
    __syncthreads();

    const int row = t >> 6;          // 0/1
    const int c2  = t & 63;          // 64 col-pairs: 0-31 -> proj_i, 32-63 -> proj_j
    const bool isj = c2 >= 32;
    const int p = (c2 & 31) * 2;
    const float* __restrict__ Wc = W + (isj ? DIM * PDIM : 0) + p;

    float a0 = 0.f, a1 = 0.f, b0 = 0.f, b1 = 0.f;   // 4 independent chains
#pragma unroll 8
    for (int d = 0; d < DIM; d += 2) {
        const float2 w0 = *(const float2*)(Wc + (size_t)d * PDIM);
        const float2 w1 = *(const float2*)(Wc + (size_t)(d + 1) * PDIM);
        const float sv0 = s[row][d];
        const float sv1 = s[row][d + 1];
        a0 = fmaf(sv0, w0.x, a0);
        a1 = fmaf(sv0, w0.y, a1);
        b0 = fmaf(sv1, w1.x, b0);
        b1 = fmaf(sv1, w1.y, b1);
    }
    float v0 = a0 + b0, v1 = a1 + b1;

    const int r = rb + row;
    if (!isj) {
        *(float2*)(g_proj_i + (size_t)r * PDIM + p) = make_float2(v0, v1);
    } else {
        v0 += bias[p];
        v1 += bias[p + 1];
        *(float2*)(g_proj_j + (size_t)r * PDIM + p) = make_float2(v0, v1);
        const int b = r >> 10, n = r & (NSEQ - 1);
        g_proj_jT[((size_t)b * PDIM + p) * NSEQ + n]     = v0;
        g_proj_jT[((size_t)b * PDIM + p + 1) * NSEQ + n] = v1;
    }
}

// ---------------------------------------------------------------------------
// Kernel 2 (tiny): per-row {mean, mean-of-squares} for both projections.
// ---------------------------------------------------------------------------
__global__ __launch_bounds__(256) void stats_kernel()
{
    const int gw = (blockIdx.x * 256 + threadIdx.x) >> 5;
    const int lane = threadIdx.x & 31;
    const bool is_j = gw >= NROWS;
    const int row = is_j ? gw - NROWS : gw;
    const float* src = is_j ? g_proj_j : g_proj_i;

    const float2 v = *(const float2*)(src + (size_t)row * PDIM + lane * 2);
    float s = v.x + v.y;
    float q = fmaf(v.x, v.x, v.y * v.y);
#pragma unroll
    for (int off = 16; off > 0; off >>= 1) {
        s += __shfl_xor_sync(0xffffffffu, s, off);
        q += __shfl_xor_sync(0xffffffffu, q, off);
    }
    if (lane == 0) {
        const float inv64 = 1.0f / 64.0f;
        float2 o = make_float2(s * inv64, q * inv64);
        if (is_j) g_mt_j[row] = o; else g_mt_i[row] = o;
    }
}

// ---------------------------------------------------------------------------
// Kernel 3: block = (b, 4 i-rows).
// Prologue: dot(a_ii, c_j) for all 4x1024 pairs via transposed proj_j
//           -> {mu, rinv} in smem. Main loop: NO reductions; streaming stores.
// ---------------------------------------------------------------------------
__global__ __launch_bounds__(256) void pair_kernel(
    const float* __restrict__ gamma, const float* __restrict__ beta,
    const float* __restrict__ embed, float* __restrict__ out)
{
    __shared__ __align__(16) float2 s_d[IT][NSEQ];   // {mu, rinv}  32 KB
    __shared__ float s_a[IT][PDIM];                  // 1 KB

    const int i0 = blockIdx.x * IT;
    const int b  = blockIdx.y;
    const int t  = threadIdx.x;

    s_a[t >> 6][t & 63] = g_proj_i[((size_t)(b * NSEQ + i0)) * PDIM + t];
    __syncthreads();

    // ---- prologue: thread t owns 4 consecutive j, all IT i's ----
    {
        const int j0 = t * 4;
        const float* __restrict__ cT = g_proj_jT + (size_t)b * PDIM * NSEQ + j0;
        float acc[IT][4] = {};
#pragma unroll 4
        for (int p = 0; p < PDIM; p++) {
            const float4 c4 = *(const float4*)(cT + (size_t)p * NSEQ);
#pragma unroll
            for (int ii = 0; ii < IT; ii++) {
                const float av = s_a[ii][p];
                acc[ii][0] = fmaf(av, c4.x, acc[ii][0]);
                acc[ii][1] = fmaf(av, c4.y, acc[ii][1]);
                acc[ii][2] = fmaf(av, c4.z, acc[ii][2]);
                acc[ii][3] = fmaf(av, c4.w, acc[ii][3]);
            }
        }
        float2 mti[IT];
#pragma unroll
        for (int ii = 0; ii < IT; ii++) mti[ii] = g_mt_i[b * NSEQ + i0 + ii];

        const float inv32 = 1.0f / 32.0f;
#pragma unroll
        for (int jj = 0; jj < 4; jj++) {
            const float2 mtj = g_mt_j[b * NSEQ + j0 + jj];
#pragma unroll
            for (int ii = 0; ii < IT; ii++) {
                const float mu  = mti[ii].x + mtj.x;
                const float e2  = fmaf(acc[ii][jj], inv32, mti[ii].y + mtj.y);
                const float var = fmaf(-mu, mu, e2);
                s_d[ii][j0 + jj] = make_float2(mu, rsqrtf(var + 1e-5f));
            }
        }
    }

    const int lane = t & 31;
    const int w = t >> 5;
    const int h = lane >> 4;
    const int li = lane & 15;

    const float4 gm   = *(const float4*)(gamma + li * 4);
    const float4 bt   = *(const float4*)(beta + li * 4);
    const float4 e_lo = *(const float4*)(embed + li * 4);
    const float4 e_hi = *(const float4*)(embed + 2 * MAXREL * PDIM + li * 4);

    __syncthreads();   // s_d ready

    float4 a[IT];
#pragma unroll
    for (int ii = 0; ii < IT; ii++)
        a[ii] = *(const float4*)&s_a[ii][li * 4];

    const float* __restrict__ pj = g_proj_j + (size_t)b * NSEQ * PDIM;
    float* obase = out + ((size_t)(b * NSEQ + i0)) * NSEQ * PDIM + li * 4;

#pragma unroll 2
    for (int jb = 0; jb < NSEQ; jb += 16) {
        const int j = jb + w * 2 + h;
        const float4 c = *(const float4*)(pj + (size_t)j * PDIM + li * 4);

#pragma unroll
        for (int ii = 0; ii < IT; ii++) {
            const float2 mr = s_d[ii][j];
            const float mu = mr.x, rinv = mr.y;

            float4 x;
            x.x = a[ii].x + c.x; x.y = a[ii].y + c.y;
            x.z = a[ii].z + c.z; x.w = a[ii].w + c.w;

            const float rgx = rinv * gm.x, rgy = rinv * gm.y;
            const float rgz = rinv * gm.z, rgw = rinv * gm.w;
            const float bx = fmaf(-mu, rgx, bt.x), by = fmaf(-mu, rgy, bt.y);
            const float bz = fmaf(-mu, rgz, bt.z), bw = fmaf(-mu, rgw, bt.w);

            float4 y;
            y.x = fmaxf(fmaf(x.x, rgx, bx), 0.f);
            y.y = fmaxf(fmaf(x.y, rgy, by), 0.f);
            y.z = fmaxf(fmaf(x.z, rgz, bz), 0.f);
            y.w = fmaxf(fmaf(x.w, rgw, bw), 0.f);

            const int dji = j - (i0 + ii);
            float4 e;
            if (dji <= -MAXREL)      e = e_lo;
            else if (dji >= MAXREL)  e = e_hi;
            else e = *(const float4*)(embed + (dji + MAXREL) * PDIM + li * 4);

            y.x += e.x; y.y += e.y; y.z += e.z; y.w += e.w;

            // streaming store: output is never re-read; keep L2 for proj_j
            __stcs((float4*)(obase + (size_t)ii * NSEQ * PDIM + (size_t)j * PDIM), y);
        }
    }
}

extern "C" void kernel_launch(void* const* d_in, const int* in_sizes, int n_in,
                              void* d_out, int out_size)
{
    const float* single = (const float*)d_in[0];
    const float* W      = (const float*)d_in[1];
    const float* bias   = (const float*)d_in[2];
    const float* gamma  = (const float*)d_in[3];
    const float* beta   = (const float*)d_in[4];
    const float* embed  = (const float*)d_in[5];
    float* out = (float*)d_out;

    proj_kernel<<<NROWS / PROWS, 128>>>(single, W, bias);

    stats_kernel<<<(2 * NROWS) / 8, 256>>>();

    dim3 grid(NSEQ / IT, BATCH);
    pair_kernel<<<grid, 256>>>(gamma, beta, embed, out);
}

// round 13
// speedup vs baseline: 1.0040x; 1.0040x over previous
#include <cuda_runtime.h>
#include <cuda_bf16.h>

#define BATCH 2
#define NSEQ 1024
#define DIM 256
#define PDIM 64
#define MAXREL 32
#define NEMBED (2 * MAXREL + 1)
#define NROWS (BATCH * NSEQ)
#define IT 4        // i-rows per block in pair_kernel
#define PTILE_R 16  // rows per proj block
#define PKC 64      // K-chunk in proj

// Scratch
__device__ float g_proj_i[NROWS * PDIM];
__device__ float g_proj_j[NROWS * PDIM];
__device__ float g_proj_jT[BATCH * PDIM * NSEQ];   // [b][p][j] transposed copy
__device__ __align__(16) float2 g_mt_i[NROWS];     // {mean, mean-of-squares}
__device__ __align__(16) float2 g_mt_j[NROWS];

// ---------------------------------------------------------------------------
// Kernel 1: projections as a smem-tiled GEMM.
// Block: 128 threads -> tile 16 rows x 128 cols (cols 0-63 = proj_i, 64-127 =
// proj_j). Thread = (colgroup cg 0-15, rowgroup rg 0-7) -> 2 rows x 8 cols,
// 16 accumulators. K in 4 chunks of 64 staged in smem.
// NOTE: sA has NO padding — compute reads sA[row][k] as scalar broadcast
// (conflict-free at any stride), and staging needs 16B-aligned rows.
// ---------------------------------------------------------------------------
__global__ __launch_bounds__(128) void proj_kernel(
    const float* __restrict__ single, const float* __restrict__ W,
    const float* __restrict__ bias)
{
    __shared__ __align__(16) float sA[PTILE_R][PKC];      // 4 KB, stride 256 B
    __shared__ __align__(16) float sW[PKC][128];          // 32 KB

    const int rb = blockIdx.x * PTILE_R;
    const int t  = threadIdx.x;
    const int cg = t & 15;
    const int rg = t >> 4;       // 0..7

    float acc[2][8] = {};

    for (int kc = 0; kc < DIM; kc += PKC) {
        // stage A chunk: 16 rows x 64 floats = 256 float4, 2 per thread
#pragma unroll
        for (int rep = 0; rep < 2; rep++) {
            const int idx = rep * 128 + t;
            const int row = idx >> 4, c4 = (idx & 15) * 4;
            *(float4*)&sA[row][c4] =
                *(const float4*)(single + (size_t)(rb + row) * DIM + kc + c4);
        }
        // stage W chunk: 64 k-rows x 128 cols = 2048 float4, 16 per thread
#pragma unroll
        for (int rep = 0; rep < 16; rep++) {
            const int idx = rep * 128 + t;
            const int k = idx >> 5, c = (idx & 31) * 4;
            const float* src = (c < 64)
                ? (W + (size_t)(kc + k) * PDIM + c)
                : (W + (size_t)(DIM + kc + k) * PDIM + (c - 64));
            *(float4*)&sW[k][c] = *(const float4*)src;
        }
        __syncthreads();

#pragma unroll 4
        for (int k = 0; k < PKC; k++) {
            const float a0 = sA[rg * 2 + 0][k];
            const float a1 = sA[rg * 2 + 1][k];
            const float4 w0 = *(const float4*)&sW[k][cg * 4];        // i-half
            const float4 w1 = *(const float4*)&sW[k][64 + cg * 4];   // j-half
            acc[0][0] = fmaf(a0, w0.x, acc[0][0]);
            acc[0][1] = fmaf(a0, w0.y, acc[0][1]);
            acc[0][2] = fmaf(a0, w0.z, acc[0][2]);
            acc[0][3] = fmaf(a0, w0.w, acc[0][3]);
            acc[0][4] = fmaf(a0, w1.x, acc[0][4]);
            acc[0][5] = fmaf(a0, w1.y, acc[0][5]);
            acc[0][6] = fmaf(a0, w1.z, acc[0][6]);
            acc[0][7] = fmaf(a0, w1.w, acc[0][7]);
            acc[1][0] = fmaf(a1, w0.x, acc[1][0]);
            acc[1][1] = fmaf(a1, w0.y, acc[1][1]);
            acc[1][2] = fmaf(a1, w0.z, acc[1][2]);
            acc[1][3] = fmaf(a1, w0.w, acc[1][3]);
            acc[1][4] = fmaf(a1, w1.x, acc[1][4]);
            acc[1][5] = fmaf(a1, w1.y, acc[1][5]);
            acc[1][6] = fmaf(a1, w1.z, acc[1][6]);
            acc[1][7] = fmaf(a1, w1.w, acc[1][7]);
        }
        __syncthreads();
    }

    const int p = cg * 4;
    const float4 bi = *(const float4*)(bias + p);
#pragma unroll
    for (int r = 0; r < 2; r++) {
        const int row = rb + rg * 2 + r;
        *(float4*)(g_proj_i + (size_t)row * PDIM + p) =
            make_float4(acc[r][0], acc[r][1], acc[r][2], acc[r][3]);

        const float v0 = acc[r][4] + bi.x;
        const float v1 = acc[r][5] + bi.y;
        const float v2 = acc[r][6] + bi.z;
        const float v3 = acc[r][7] + bi.w;
        *(float4*)(g_proj_j + (size_t)row * PDIM + p) = make_float4(v0, v1, v2, v3);

        const int b = row >> 10, n = row & (NSEQ - 1);
        float* jT = g_proj_jT + ((size_t)b * PDIM + p) * NSEQ + n;
        jT[0]        = v0;
        jT[NSEQ]     = v1;
        jT[2 * NSEQ] = v2;
        jT[3 * NSEQ] = v3;
    }
}

// ---------------------------------------------------------------------------
// Kernel 2 (tiny): per-row {mean, mean-of-squares} for both projections.
// ---------------------------------------------------------------------------
__global__ __launch_bounds__(256) void stats_kernel()
{
    const int gw = (blockIdx.x * 256 + threadIdx.x) >> 5;
    const int lane = threadIdx.x & 31;
    const bool is_j = gw >= NROWS;
    const int row = is_j ? gw - NROWS : gw;
    const float* src = is_j ? g_proj_j : g_proj_i;

    const float2 v = *(const float2*)(src + (size_t)row * PDIM + lane * 2);
    float s = v.x + v.y;
    float q = fmaf(v.x, v.x, v.y * v.y);
#pragma unroll
    for (int off = 16; off > 0; off >>= 1) {
        s += __shfl_xor_sync(0xffffffffu, s, off);
        q += __shfl_xor_sync(0xffffffffu, q, off);
    }
    if (lane == 0) {
        const float inv64 = 1.0f / 64.0f;
        float2 o = make_float2(s * inv64, q * inv64);
        if (is_j) g_mt_j[row] = o; else g_mt_i[row] = o;
    }
}

// ---------------------------------------------------------------------------
// Kernel 3: block = (b, 4 i-rows).
// Prologue: dot(a_ii, c_j) for all 4x1024 pairs via transposed proj_j
//           -> {mu, rinv} in smem. Main loop: NO reductions; streaming stores.
// ---------------------------------------------------------------------------
__global__ __launch_bounds__(256) void pair_kernel(
    const float* __restrict__ gamma, const float* __restrict__ beta,
    const float* __restrict__ embed, float* __restrict__ out)
{
    __shared__ __align__(16) float2 s_d[IT][NSEQ];   // {mu, rinv}  32 KB
    __shared__ float s_a[IT][PDIM];                  // 1 KB

    const int i0 = blockIdx.x * IT;
    const int b  = blockIdx.y;
    const int t  = threadIdx.x;

    s_a[t >> 6][t & 63] = g_proj_i[((size_t)(b * NSEQ + i0)) * PDIM + t];
    __syncthreads();

    // ---- prologue: thread t owns 4 consecutive j, all IT i's ----
    {
        const int j0 = t * 4;
        const float* __restrict__ cT = g_proj_jT + (size_t)b * PDIM * NSEQ + j0;
        float acc[IT][4] = {};
#pragma unroll 4
        for (int p = 0; p < PDIM; p++) {
            const float4 c4 = *(const float4*)(cT + (size_t)p * NSEQ);
#pragma unroll
            for (int ii = 0; ii < IT; ii++) {
                const float av = s_a[ii][p];
                acc[ii][0] = fmaf(av, c4.x, acc[ii][0]);
                acc[ii][1] = fmaf(av, c4.y, acc[ii][1]);
                acc[ii][2] = fmaf(av, c4.z, acc[ii][2]);
                acc[ii][3] = fmaf(av, c4.w, acc[ii][3]);
            }
        }
        float2 mti[IT];
#pragma unroll
        for (int ii = 0; ii < IT; ii++) mti[ii] = g_mt_i[b * NSEQ + i0 + ii];

        const float inv32 = 1.0f / 32.0f;
#pragma unroll
        for (int jj = 0; jj < 4; jj++) {
            const float2 mtj = g_mt_j[b * NSEQ + j0 + jj];
#pragma unroll
            for (int ii = 0; ii < IT; ii++) {
                const float mu  = mti[ii].x + mtj.x;
                const float e2  = fmaf(acc[ii][jj], inv32, mti[ii].y + mtj.y);
                const float var = fmaf(-mu, mu, e2);
                s_d[ii][j0 + jj] = make_float2(mu, rsqrtf(var + 1e-5f));
            }
        }
    }

    const int lane = t & 31;
    const int w = t >> 5;
    const int h = lane >> 4;
    const int li = lane & 15;

    const float4 gm   = *(const float4*)(gamma + li * 4);
    const float4 bt   = *(const float4*)(beta + li * 4);
    const float4 e_lo = *(const float4*)(embed + li * 4);
    const float4 e_hi = *(const float4*)(embed + 2 * MAXREL * PDIM + li * 4);

    __syncthreads();   // s_d ready

    float4 a[IT];
#pragma unroll
    for (int ii = 0; ii < IT; ii++)
        a[ii] = *(const float4*)&s_a[ii][li * 4];

    const float* __restrict__ pj = g_proj_j + (size_t)b * NSEQ * PDIM;
    float* obase = out + ((size_t)(b * NSEQ + i0)) * NSEQ * PDIM + li * 4;

#pragma unroll 2
    for (int jb = 0; jb < NSEQ; jb += 16) {
        const int j = jb + w * 2 + h;
        const float4 c = *(const float4*)(pj + (size_t)j * PDIM + li * 4);

#pragma unroll
        for (int ii = 0; ii < IT; ii++) {
            const float2 mr = s_d[ii][j];
            const float mu = mr.x, rinv = mr.y;

            float4 x;
            x.x = a[ii].x + c.x; x.y = a[ii].y + c.y;
            x.z = a[ii].z + c.z; x.w = a[ii].w + c.w;

            const float rgx = rinv * gm.x, rgy = rinv * gm.y;
            const float rgz = rinv * gm.z, rgw = rinv * gm.w;
            const float bx = fmaf(-mu, rgx, bt.x), by = fmaf(-mu, rgy, bt.y);
            const float bz = fmaf(-mu, rgz, bt.z), bw = fmaf(-mu, rgw, bt.w);

            float4 y;
            y.x = fmaxf(fmaf(x.x, rgx, bx), 0.f);
            y.y = fmaxf(fmaf(x.y, rgy, by), 0.f);
            y.z = fmaxf(fmaf(x.z, rgz, bz), 0.f);
            y.w = fmaxf(fmaf(x.w, rgw, bw), 0.f);

            const int dji = j - (i0 + ii);
            float4 e;
            if (dji <= -MAXREL)      e = e_lo;
            else if (dji >= MAXREL)  e = e_hi;
            else e = *(const float4*)(embed + (dji + MAXREL) * PDIM + li * 4);

            y.x += e.x; y.y += e.y; y.z += e.z; y.w += e.w;

            // streaming store: output is never re-read; keep L2 for proj_j
            __stcs((float4*)(obase + (size_t)ii * NSEQ * PDIM + (size_t)j * PDIM), y);
        }
    }
}

extern "C" void kernel_launch(void* const* d_in, const int* in_sizes, int n_in,
                              void* d_out, int out_size)
{
    const float* single = (const float*)d_in[0];
    const float* W      = (const float*)d_in[1];
    const float* bias   = (const float*)d_in[2];
    const float* gamma  = (const float*)d_in[3];
    const float* beta   = (const float*)d_in[4];
    const float* embed  = (const float*)d_in[5];
    float* out = (float*)d_out;

    proj_kernel<<<NROWS / PTILE_R, 128>>>(single, W, bias);

    stats_kernel<<<(2 * NROWS) / 8, 256>>>();

    dim3 grid(NSEQ / IT, BATCH);
    pair_kernel<<<grid, 256>>>(gamma, beta, embed, out);
}

// round 14
// speedup vs baseline: 1.0546x; 1.0503x over previous
#include <cuda_runtime.h>
#include <cuda_bf16.h>

#define BATCH 2
#define NSEQ 1024
#define DIM 256
#define PDIM 64
#define MAXREL 32
#define NEMBED (2 * MAXREL + 1)
#define NROWS (BATCH * NSEQ)
#define IT 4        // i-rows per block in pair_kernel
#define PTILE_R 16  // rows per proj tile
#define PKC 64      // K-chunk per proj block
#define NKC (DIM / PKC)   // 4 k-chunks

// Scratch
__device__ float g_part_i[NKC * NROWS * PDIM];     // per-kc partial sums
__device__ float g_part_j[NKC * NROWS * PDIM];
__device__ float g_proj_i[NROWS * PDIM];
__device__ float g_proj_j[NROWS * PDIM];
__device__ float g_proj_jT[BATCH * PDIM * NSEQ];   // [b][p][j] transposed copy
__device__ __align__(16) float2 g_mt_i[NROWS];     // {mean, mean-of-squares}
__device__ __align__(16) float2 g_mt_j[NROWS];

// ---------------------------------------------------------------------------
// Kernel 1: K-split tiled GEMM. Block = (row-tile 16, one 64-k chunk).
// grid = 128 x 4 = 512 blocks (~3.5/SM) -> latency hidden by block overlap.
// Thread = 2 rows x 8 cols, 16 accumulators; partials to g_part_*.
// ---------------------------------------------------------------------------
__global__ __launch_bounds__(128) void proj_kernel(
    const float* __restrict__ single, const float* __restrict__ W)
{
    __shared__ __align__(16) float sA[PTILE_R][PKC];   // 4 KB
    __shared__ __align__(16) float sW[PKC][128];       // 32 KB

    const int rb  = blockIdx.x * PTILE_R;
    const int kci = blockIdx.y;
    const int kc  = kci * PKC;
    const int t   = threadIdx.x;
    const int cg  = t & 15;
    const int rg  = t >> 4;

    // stage A chunk: 16 rows x 64 floats = 256 float4, 2 per thread
#pragma unroll
    for (int rep = 0; rep < 2; rep++) {
        const int idx = rep * 128 + t;
        const int row = idx >> 4, c4 = (idx & 15) * 4;
        *(float4*)&sA[row][c4] =
            *(const float4*)(single + (size_t)(rb + row) * DIM + kc + c4);
    }
    // stage W chunk: 64 k-rows x 128 cols = 2048 float4, 16 per thread
#pragma unroll
    for (int rep = 0; rep < 16; rep++) {
        const int idx = rep * 128 + t;
        const int k = idx >> 5, c = (idx & 31) * 4;
        const float* src = (c < 64)
            ? (W + (size_t)(kc + k) * PDIM + c)
            : (W + (size_t)(DIM + kc + k) * PDIM + (c - 64));
        *(float4*)&sW[k][c] = *(const float4*)src;
    }
    __syncthreads();

    float acc[2][8] = {};
#pragma unroll 4
    for (int k = 0; k < PKC; k++) {
        const float a0 = sA[rg * 2 + 0][k];
        const float a1 = sA[rg * 2 + 1][k];
        const float4 w0 = *(const float4*)&sW[k][cg * 4];        // i-half
        const float4 w1 = *(const float4*)&sW[k][64 + cg * 4];   // j-half
        acc[0][0] = fmaf(a0, w0.x, acc[0][0]);
        acc[0][1] = fmaf(a0, w0.y, acc[0][1]);
        acc[0][2] = fmaf(a0, w0.z, acc[0][2]);
        acc[0][3] = fmaf(a0, w0.w, acc[0][3]);
        acc[0][4] = fmaf(a0, w1.x, acc[0][4]);
        acc[0][5] = fmaf(a0, w1.y, acc[0][5]);
        acc[0][6] = fmaf(a0, w1.z, acc[0][6]);
        acc[0][7] = fmaf(a0, w1.w, acc[0][7]);
        acc[1][0] = fmaf(a1, w0.x, acc[1][0]);
        acc[1][1] = fmaf(a1, w0.y, acc[1][1]);
        acc[1][2] = fmaf(a1, w0.z, acc[1][2]);
        acc[1][3] = fmaf(a1, w0.w, acc[1][3]);
        acc[1][4] = fmaf(a1, w1.x, acc[1][4]);
        acc[1][5] = fmaf(a1, w1.y, acc[1][5]);
        acc[1][6] = fmaf(a1, w1.z, acc[1][6]);
        acc[1][7] = fmaf(a1, w1.w, acc[1][7]);
    }

    const int p = cg * 4;
#pragma unroll
    for (int r = 0; r < 2; r++) {
        const size_t row = rb + rg * 2 + r;
        const size_t off = ((size_t)kci * NROWS + row) * PDIM + p;
        *(float4*)(g_part_i + off) =
            make_float4(acc[r][0], acc[r][1], acc[r][2], acc[r][3]);
        *(float4*)(g_part_j + off) =
            make_float4(acc[r][4], acc[r][5], acc[r][6], acc[r][7]);
    }
}

// ---------------------------------------------------------------------------
// Kernel 2: merge the 4 K-partials (+bias for j), compute per-row stats,
// write proj_i / proj_j / proj_jT. One warp per (row, type); lane = 2 cols.
// ---------------------------------------------------------------------------
__global__ __launch_bounds__(256) void stats_kernel(const float* __restrict__ bias)
{
    const int gw = (blockIdx.x * 256 + threadIdx.x) >> 5;
    const int lane = threadIdx.x & 31;
    const bool is_j = gw >= NROWS;
    const int row = is_j ? gw - NROWS : gw;
    const float* __restrict__ part = is_j ? g_part_j : g_part_i;
    const int p2 = lane * 2;

    float2 v = make_float2(0.f, 0.f);
#pragma unroll
    for (int c = 0; c < NKC; c++) {
        const float2 pv = *(const float2*)(part + ((size_t)c * NROWS + row) * PDIM + p2);
        v.x += pv.x; v.y += pv.y;
    }
    if (is_j) { v.x += bias[p2]; v.y += bias[p2 + 1]; }

    float s = v.x + v.y;
    float q = fmaf(v.x, v.x, v.y * v.y);
#pragma unroll
    for (int off = 16; off > 0; off >>= 1) {
        s += __shfl_xor_sync(0xffffffffu, s, off);
        q += __shfl_xor_sync(0xffffffffu, q, off);
    }

    if (!is_j) {
        *(float2*)(g_proj_i + (size_t)row * PDIM + p2) = v;
        if (lane == 0)
            g_mt_i[row] = make_float2(s * (1.0f / 64.0f), q * (1.0f / 64.0f));
    } else {
        *(float2*)(g_proj_j + (size_t)row * PDIM + p2) = v;
        const int b = row >> 10, n = row & (NSEQ - 1);
        float* jT = g_proj_jT + ((size_t)b * PDIM + p2) * NSEQ + n;
        jT[0]    = v.x;
        jT[NSEQ] = v.y;
        if (lane == 0)
            g_mt_j[row] = make_float2(s * (1.0f / 64.0f), q * (1.0f / 64.0f));
    }
}

// ---------------------------------------------------------------------------
// Kernel 3: block = (b, 4 i-rows).
// Prologue: dot(a_ii, c_j) for all 4x1024 pairs via transposed proj_j
//           -> {mu, rinv} in smem. Main loop: NO reductions; streaming stores.
// ---------------------------------------------------------------------------
__global__ __launch_bounds__(256) void pair_kernel(
    const float* __restrict__ gamma, const float* __restrict__ beta,
    const float* __restrict__ embed, float* __restrict__ out)
{
    __shared__ __align__(16) float2 s_d[IT][NSEQ];   // {mu, rinv}  32 KB
    __shared__ float s_a[IT][PDIM];                  // 1 KB

    const int i0 = blockIdx.x * IT;
    const int b  = blockIdx.y;
    const int t  = threadIdx.x;

    s_a[t >> 6][t & 63] = g_proj_i[((size_t)(b * NSEQ + i0)) * PDIM + t];
    __syncthreads();

    // ---- prologue: thread t owns 4 consecutive j, all IT i's ----
    {
        const int j0 = t * 4;
        const float* __restrict__ cT = g_proj_jT + (size_t)b * PDIM * NSEQ + j0;
        float acc[IT][4] = {};
#pragma unroll 4
        for (int p = 0; p < PDIM; p++) {
            const float4 c4 = *(const float4*)(cT + (size_t)p * NSEQ);
#pragma unroll
            for (int ii = 0; ii < IT; ii++) {
                const float av = s_a[ii][p];
                acc[ii][0] = fmaf(av, c4.x, acc[ii][0]);
                acc[ii][1] = fmaf(av, c4.y, acc[ii][1]);
                acc[ii][2] = fmaf(av, c4.z, acc[ii][2]);
                acc[ii][3] = fmaf(av, c4.w, acc[ii][3]);
            }
        }
        float2 mti[IT];
#pragma unroll
        for (int ii = 0; ii < IT; ii++) mti[ii] = g_mt_i[b * NSEQ + i0 + ii];

        const float inv32 = 1.0f / 32.0f;
#pragma unroll
        for (int jj = 0; jj < 4; jj++) {
            const float2 mtj = g_mt_j[b * NSEQ + j0 + jj];
#pragma unroll
            for (int ii = 0; ii < IT; ii++) {
                const float mu  = mti[ii].x + mtj.x;
                const float e2  = fmaf(acc[ii][jj], inv32, mti[ii].y + mtj.y);
                const float var = fmaf(-mu, mu, e2);
                s_d[ii][j0 + jj] = make_float2(mu, rsqrtf(var + 1e-5f));
            }
        }
    }

    const int lane = t & 31;
    const int w = t >> 5;
    const int h = lane >> 4;
    const int li = lane & 15;

    const float4 gm   = *(const float4*)(gamma + li * 4);
    const float4 bt   = *(const float4*)(beta + li * 4);
    const float4 e_lo = *(const float4*)(embed + li * 4);
    const float4 e_hi = *(const float4*)(embed + 2 * MAXREL * PDIM + li * 4);

    __syncthreads();   // s_d ready

    float4 a[IT];
#pragma unroll
    for (int ii = 0; ii < IT; ii++)
        a[ii] = *(const float4*)&s_a[ii][li * 4];

    const float* __restrict__ pj = g_proj_j + (size_t)b * NSEQ * PDIM;
    float* obase = out + ((size_t)(b * NSEQ + i0)) * NSEQ * PDIM + li * 4;

#pragma unroll 2
    for (int jb = 0; jb < NSEQ; jb += 16) {
        const int j = jb + w * 2 + h;
        const float4 c = *(const float4*)(pj + (size_t)j * PDIM + li * 4);

#pragma unroll
        for (int ii = 0; ii < IT; ii++) {
            const float2 mr = s_d[ii][j];
            const float mu = mr.x, rinv = mr.y;

            float4 x;
            x.x = a[ii].x + c.x; x.y = a[ii].y + c.y;
            x.z = a[ii].z + c.z; x.w = a[ii].w + c.w;

            const float rgx = rinv * gm.x, rgy = rinv * gm.y;
            const float rgz = rinv * gm.z, rgw = rinv * gm.w;
            const float bx = fmaf(-mu, rgx, bt.x), by = fmaf(-mu, rgy, bt.y);
            const float bz = fmaf(-mu, rgz, bt.z), bw = fmaf(-mu, rgw, bt.w);

            float4 y;
            y.x = fmaxf(fmaf(x.x, rgx, bx), 0.f);
            y.y = fmaxf(fmaf(x.y, rgy, by), 0.f);
            y.z = fmaxf(fmaf(x.z, rgz, bz), 0.f);
            y.w = fmaxf(fmaf(x.w, rgw, bw), 0.f);

            const int dji = j - (i0 + ii);
            float4 e;
            if (dji <= -MAXREL)      e = e_lo;
            else if (dji >= MAXREL)  e = e_hi;
            else e = *(const float4*)(embed + (dji + MAXREL) * PDIM + li * 4);

            y.x += e.x; y.y += e.y; y.z += e.z; y.w += e.w;

            // streaming store: output is never re-read; keep L2 for proj_j
            __stcs((float4*)(obase + (size_t)ii * NSEQ * PDIM + (size_t)j * PDIM), y);
        }
    }
}

extern "C" void kernel_launch(void* const* d_in, const int* in_sizes, int n_in,
                              void* d_out, int out_size)
{
    const float* single = (const float*)d_in[0];
    const float* W      = (const float*)d_in[1];
    const float* bias   = (const float*)d_in[2];
    const float* gamma  = (const float*)d_in[3];
    const float* beta   = (const float*)d_in[4];
    const float* embed  = (const float*)d_in[5];
    float* out = (float*)d_out;

    dim3 pgrid(NROWS / PTILE_R, NKC);
    proj_kernel<<<pgrid, 128>>>(single, W);

    stats_kernel<<<(2 * NROWS) / 8, 256>>>(bias);

    dim3 grid(NSEQ / IT, BATCH);
    pair_kernel<<<grid, 256>>>(gamma, beta, embed, out);
}